// round 5
// baseline (speedup 1.0000x reference)
#include <cuda_runtime.h>
#include <math.h>
#include <stdint.h>

// ---------------- problem constants ----------------
#define Bz   16
#define T0   400
#define F0c  40
#define Hc   512
#define T1c  396
#define T3c  384
#define Kbot (Hc*Hc)   // 262144

// ---------------- scratch (device globals; no allocs allowed) ----------------
__device__ float g_x0[Bz*F0c*T0];        // transposed input [B,F0,T0]
__device__ float g_bufA[Bz*Hc*T1c];      // ping
__device__ float g_bufB[Bz*Hc*T1c];      // pong
__device__ float g_x5[Bz*Hc*T3c];        // lin5 output (raw)
__device__ float g_M[Bz*Kbot];           // pooled matrices [B,512,512]
__device__ float g_sum[Hc];              // BN stat accumulators (zero-init; re-zeroed by finalize)
__device__ float g_sumsq[Hc];
__device__ float g_scale[Hc];
__device__ float g_shift[Hc];
__device__ float g_scale4[Hc];
__device__ float g_shift4[Hc];
__device__ float g_scale5[Hc];
__device__ float g_shift5[Hc];
__device__ float g_h[Bz*Hc];             // bottleneck raw accum (atomics)
__device__ float g_hn[Bz*Hc];            // post-BN h
__device__ float g_emb[Bz*Hc];
__device__ float g_zero[Hc];             // stays zero (zero-initialized)

// ---------------- helpers ----------------
__device__ __forceinline__ uint32_t f2tf32(float x)
{
    uint32_t r;
    asm("cvt.rna.tf32.f32 %0, %1;" : "=r"(r) : "f"(x));
    return r;
}

__device__ __forceinline__ void tf32_split(float x, uint32_t& hi, uint32_t& lo)
{
    hi = f2tf32(x);
    lo = f2tf32(x - __uint_as_float(hi));
}

__device__ __forceinline__ void mma_tf32(float* d, const uint32_t* a, const uint32_t* b)
{
    asm volatile(
        "mma.sync.aligned.m16n8k8.row.col.f32.tf32.tf32.f32 "
        "{%0,%1,%2,%3}, {%4,%5,%6,%7}, {%8,%9}, {%0,%1,%2,%3};"
        : "+f"(d[0]), "+f"(d[1]), "+f"(d[2]), "+f"(d[3])
        : "r"(a[0]), "r"(a[1]), "r"(a[2]), "r"(a[3]), "r"(b[0]), "r"(b[1]));
}

__device__ __forceinline__ float relu20(float v)
{
    return fminf(fmaxf(v, 0.f), 20.f);
}

// ---------------- transpose [B,1,T,F] -> [B,F,T] ----------------
__global__ void transpose_kernel(const float* __restrict__ in, float* __restrict__ out)
{
    int idx = blockIdx.x * blockDim.x + threadIdx.x;
    if (idx >= Bz * T0 * F0c) return;
    int c = idx % F0c;
    int t = (idx / F0c) % T0;
    int b = idx / (F0c * T0);
    out[(b * F0c + c) * T0 + t] = in[idx];
}

// ---------------- TF32x3 tensor-core conv-as-GEMM, fused BN ----------------
// C[o,n] = sum_kk A[o,kk] * bnB(X[(b(n)*C + c(kk))*Tin + t(n) + kw(kk)*DIL])
// MODE 0: raw X.  MODE 1: X gets scB[c]*v+shB[c], clamp (prev-layer BN).
// MODE 2 (pooling): X gets scB[n]*v+shB[n], A gets scA[row]*v+shA[row].
// STATS: epilogue accumulates per-row sum/sumsq of (acc+bias).
// BM=64 BN=128 BK=8, 256 threads, 8 warps 2x4, warp tile 32x32, double-buffered.
// Smem strides 72/136 (== 8 mod 32) make all fragment LDS and stores bank-conflict-free.
#define ASTR 72
#define BSTR 136
template<int KW, int DIL, int MODE, bool STATS>
__global__ __launch_bounds__(256, 2)
void conv_gemm_tf32x3(const float* __restrict__ A, const float* __restrict__ bias,
                      const float* __restrict__ X, float* __restrict__ Y,
                      const float* __restrict__ scA, const float* __restrict__ shA,
                      const float* __restrict__ scB, const float* __restrict__ shB,
                      int C, int Tin, int Tout, int CK, int Ntot,
                      int strideA, int strideX, int strideY)
{
    A += (size_t)blockIdx.z * strideA;
    X += (size_t)blockIdx.z * strideX;
    Y += (size_t)blockIdx.z * strideY;

    __shared__ uint32_t AsH[2][8][ASTR];
    __shared__ uint32_t AsL[2][8][ASTR];
    __shared__ uint32_t BsH[2][8][BSTR];
    __shared__ uint32_t BsL[2][8][BSTR];
    __shared__ float sScB[Hc];
    __shared__ float sShB[Hc];

    const int tid  = threadIdx.x;
    const int lane = tid & 31;
    const int warp = tid >> 5;
    const int wm = warp >> 2;      // 0..1  (32 rows each)
    const int wn = warp & 3;       // 0..3  (32 cols each)
    const int oBase = blockIdx.y * 64;
    const int nBase = blockIdx.x * 128;

    float acc[2][4][4];
    #pragma unroll
    for (int i = 0; i < 2; i++)
        #pragma unroll
        for (int j = 0; j < 4; j++)
            #pragma unroll
            for (int r = 0; r < 4; r++) acc[i][j][r] = 0.f;

    // A loader: 64 rows x 8 cols / 256 thr = 2 elems: float2
    const int aRow = tid & 63;
    const int aCol = (tid >> 6) * 2;
    // B loader: 8 x 128 / 256 = 4 elems: n = tid&127, kk = (tid>>7) + 2*p
    const int bN  = tid & 127;
    const int bK0 = tid >> 7;

    const int nIdx = nBase + bN;
    const bool nValid = (nIdx < Ntot);
    int nb = 0, nt = 0;
    if (nValid) { nb = nIdx / Tout; nt = nIdx - nb * Tout; }
    const float* Xbase = X + ((size_t)nb * C) * Tin + nt;

    // per-thread BN constants for MODE 2
    float aS = 1.f, aSh = 0.f, bS = 1.f, bSh = 0.f;
    if (MODE == 2) {
        aS  = scA[oBase + aRow];
        aSh = shA[oBase + aRow];
        bS  = scB[nIdx & (Hc - 1)];
        bSh = shB[nIdx & (Hc - 1)];
    }
    if (MODE == 1) {
        for (int i = tid; i < C; i += 256) {
            sScB[i] = scB[i];
            sShB[i] = shB[i];
        }
        __syncthreads();
    }

    float pa[2], pb[4];

    // prefetch k0 = 0
    {
        const float2 av = *(const float2*)(A + (size_t)(oBase + aRow) * CK + aCol);
        pa[0] = av.x; pa[1] = av.y;
        if (MODE == 2) {
            pa[0] = relu20(aS * pa[0] + aSh);
            pa[1] = relu20(aS * pa[1] + aSh);
        }
        #pragma unroll
        for (int p = 0; p < 4; p++) {
            int kkg = bK0 + 2 * p;
            int c = kkg / KW;
            int kw = kkg - c * KW;
            float v = nValid ? Xbase[c * Tin + kw * DIL] : 0.f;
            if (MODE == 1) v = relu20(sScB[c] * v + sShB[c]);
            if (MODE == 2) v = relu20(bS * v + bSh);
            pb[p] = v;
        }
    }

    int pbuf = 0;
    for (int k0 = 0; k0 < CK; k0 += 8) {
        // stage current tile (hi/lo split) into buffer pbuf
        #pragma unroll
        for (int j = 0; j < 2; j++) {
            uint32_t h, l;
            tf32_split(pa[j], h, l);
            AsH[pbuf][aCol + j][aRow] = h;
            AsL[pbuf][aCol + j][aRow] = l;
        }
        #pragma unroll
        for (int p = 0; p < 4; p++) {
            uint32_t h, l;
            tf32_split(pb[p], h, l);
            BsH[pbuf][bK0 + 2 * p][bN] = h;
            BsL[pbuf][bK0 + 2 * p][bN] = l;
        }
        __syncthreads();

        // prefetch next tile (overlaps with MMA below)
        if (k0 + 8 < CK) {
            const float2 av = *(const float2*)(A + (size_t)(oBase + aRow) * CK + k0 + 8 + aCol);
            pa[0] = av.x; pa[1] = av.y;
            if (MODE == 2) {
                pa[0] = relu20(aS * pa[0] + aSh);
                pa[1] = relu20(aS * pa[1] + aSh);
            }
            #pragma unroll
            for (int p = 0; p < 4; p++) {
                int kkg = k0 + 8 + bK0 + 2 * p;
                int c = kkg / KW;
                int kw = kkg - c * KW;
                float v = nValid ? Xbase[c * Tin + kw * DIL] : 0.f;
                if (MODE == 1) v = relu20(sScB[c] * v + sShB[c]);
                if (MODE == 2) v = relu20(bS * v + bSh);
                pb[p] = v;
            }
        }

        // fragments (hi + lo); banks: 8*kk + idx -> conflict-free
        const int kk = lane & 3;
        uint32_t aH[2][4], aL[2][4];
        #pragma unroll
        for (int mt = 0; mt < 2; mt++) {
            int row = wm * 32 + mt * 16 + (lane >> 2);
            aH[mt][0] = AsH[pbuf][kk][row];     aL[mt][0] = AsL[pbuf][kk][row];
            aH[mt][1] = AsH[pbuf][kk][row + 8]; aL[mt][1] = AsL[pbuf][kk][row + 8];
            aH[mt][2] = AsH[pbuf][kk + 4][row];     aL[mt][2] = AsL[pbuf][kk + 4][row];
            aH[mt][3] = AsH[pbuf][kk + 4][row + 8]; aL[mt][3] = AsL[pbuf][kk + 4][row + 8];
        }
        uint32_t bH[4][2], bL[4][2];
        #pragma unroll
        for (int ntile = 0; ntile < 4; ntile++) {
            int col = wn * 32 + ntile * 8 + (lane >> 2);
            bH[ntile][0] = BsH[pbuf][kk][col];     bL[ntile][0] = BsL[pbuf][kk][col];
            bH[ntile][1] = BsH[pbuf][kk + 4][col]; bL[ntile][1] = BsL[pbuf][kk + 4][col];
        }
        #pragma unroll
        for (int mt = 0; mt < 2; mt++)
            #pragma unroll
            for (int ntile = 0; ntile < 4; ntile++) {
                mma_tf32(acc[mt][ntile], aH[mt], bL[ntile]);
                mma_tf32(acc[mt][ntile], aL[mt], bH[ntile]);
                mma_tf32(acc[mt][ntile], aH[mt], bH[ntile]);
            }

        pbuf ^= 1;
    }

    // epilogue: D[row, col] -> Y[(b*Hc + o)*Tout + t] + bias[o]; optional BN stats
    #pragma unroll
    for (int mt = 0; mt < 2; mt++) {
        int row0 = oBase + wm * 32 + mt * 16 + (lane >> 2);
        float b0 = bias[row0];
        float b1 = bias[row0 + 8];
        float s0 = 0.f, q0 = 0.f, s1 = 0.f, q1 = 0.f;
        #pragma unroll
        for (int ntile = 0; ntile < 4; ntile++) {
            int col0 = nBase + wn * 32 + ntile * 8 + (lane & 3) * 2;
            #pragma unroll
            for (int cc = 0; cc < 2; cc++) {
                int col = col0 + cc;
                if (col < Ntot) {
                    float v0 = acc[mt][ntile][cc]     + b0;
                    float v1 = acc[mt][ntile][2 + cc] + b1;
                    int b = col / Tout;
                    int t = col - b * Tout;
                    size_t base = ((size_t)b * Hc) * Tout + t;
                    Y[base + (size_t)row0 * Tout]       = v0;
                    Y[base + (size_t)(row0 + 8) * Tout] = v1;
                    if (STATS) {
                        s0 += v0; q0 += v0 * v0;
                        s1 += v1; q1 += v1 * v1;
                    }
                }
            }
        }
        if (STATS) {
            #pragma unroll
            for (int off = 2; off >= 1; off >>= 1) {
                s0 += __shfl_down_sync(0xffffffffu, s0, off);
                q0 += __shfl_down_sync(0xffffffffu, q0, off);
                s1 += __shfl_down_sync(0xffffffffu, s1, off);
                q1 += __shfl_down_sync(0xffffffffu, q1, off);
            }
            if ((lane & 3) == 0) {
                atomicAdd(&g_sum[row0], s0);
                atomicAdd(&g_sumsq[row0], q0);
                atomicAdd(&g_sum[row0 + 8], s1);
                atomicAdd(&g_sumsq[row0 + 8], q1);
            }
        }
    }
}

// ---------------- BN finalize: sums -> scale/shift; re-zero accumulators ----------------
__global__ void bn_finalize(const float* __restrict__ g, const float* __restrict__ be,
                            float* __restrict__ sc, float* __restrict__ sh, float invN)
{
    int c = threadIdx.x;   // 512
    float s = g_sum[c], q = g_sumsq[c];
    float m = s * invN;
    float var = q * invN - m * m;
    float a = g[c] * rsqrtf(var + 1e-5f);
    sc[c] = a;
    sh[c] = be[c] - a * m;
    g_sum[c] = 0.f;
    g_sumsq[c] = 0.f;
}

// ---------------- bottleneck: h[b,o] += sum_k M[b,k]*W[o,k] ----------------
__global__ void zero_h()
{
    g_h[blockIdx.x * blockDim.x + threadIdx.x] = 0.f;
}

__global__ __launch_bounds__(512)
void bottleneck(const float* __restrict__ W)
{
    __shared__ float Ms[Bz][512];
    int warp = threadIdx.x >> 5, lane = threadIdx.x & 31;
    int o0 = blockIdx.x * 32 + warp * 2;           // 16 warps x 2 o each
    int k0 = blockIdx.y * (Kbot / 32);             // 8192-wide K split

    float acc0[16], acc1[16];
    #pragma unroll
    for (int b = 0; b < 16; b++) { acc0[b] = 0.f; acc1[b] = 0.f; }

    for (int kt = 0; kt < Kbot / 32; kt += 512) {
        __syncthreads();
        #pragma unroll
        for (int i = 0; i < 16; i++) {
            int idx = threadIdx.x + i * 512;
            int b = idx >> 9, kk = idx & 511;
            Ms[b][kk] = g_M[b * Kbot + k0 + kt + kk];
        }
        __syncthreads();
        const float* w0p = W + (size_t)o0 * Kbot + k0 + kt;
        const float* w1p = w0p + Kbot;
        #pragma unroll
        for (int kk = lane * 4; kk < 512; kk += 128) {
            float4 w0 = *(const float4*)(w0p + kk);
            float4 w1 = *(const float4*)(w1p + kk);
            #pragma unroll
            for (int b = 0; b < 16; b++) {
                float4 m = *(const float4*)&Ms[b][kk];
                acc0[b] += w0.x * m.x + w0.y * m.y + w0.z * m.z + w0.w * m.w;
                acc1[b] += w1.x * m.x + w1.y * m.y + w1.z * m.z + w1.w * m.w;
            }
        }
    }
    #pragma unroll
    for (int b = 0; b < 16; b++) {
        float v0 = acc0[b], v1 = acc1[b];
        #pragma unroll
        for (int off = 16; off; off >>= 1) {
            v0 += __shfl_down_sync(0xffffffffu, v0, off);
            v1 += __shfl_down_sync(0xffffffffu, v1, off);
        }
        if (lane == 0) {
            atomicAdd(&g_h[b * Hc + o0], v0);
            atomicAdd(&g_h[b * Hc + o0 + 1], v1);
        }
    }
}

// ---------------- BN over batch dim (16 samples) + relu20 ----------------
__global__ void bn2d_relu(const float* __restrict__ bot_b, const float* __restrict__ gg,
                          const float* __restrict__ gb)
{
    int o = threadIdx.x;   // 512 threads
    float v[16];
    float s = 0.f, sq = 0.f;
    #pragma unroll
    for (int b = 0; b < 16; b++) {
        float x = g_h[b * Hc + o] + bot_b[o];
        v[b] = x; s += x; sq += x * x;
    }
    float m = s * (1.f / 16.f);
    float var = sq * (1.f / 16.f) - m * m;
    float a = gg[o] * rsqrtf(var + 1e-5f);
    float d = gb[o] - a * m;
    #pragma unroll
    for (int b = 0; b < 16; b++) {
        float z = a * v[b] + d;
        g_hn[b * Hc + o] = fminf(fmaxf(z, 0.f), 20.f);
    }
}

// ---------------- embedding GEMV + bias ----------------
__global__ void emb_kernel(const float* __restrict__ h, const float* __restrict__ W,
                           const float* __restrict__ bias, float* __restrict__ emb)
{
    int b = blockIdx.x;
    int warp = threadIdx.x >> 5, lane = threadIdx.x & 31;
    __shared__ float hs[512];
    hs[threadIdx.x] = h[b * Hc + threadIdx.x];
    __syncthreads();
    for (int e = warp; e < 512; e += 16) {
        float s = 0.f;
        for (int c = lane; c < 512; c += 32)
            s += hs[c] * W[e * 512 + c];
        #pragma unroll
        for (int off = 16; off; off >>= 1)
            s += __shfl_down_sync(0xffffffffu, s, off);
        if (lane == 0) emb[b * Hc + e] = s + bias[e];
    }
}

// ---------------- L2 normalize * 10 ----------------
__global__ void norm_kernel(const float* __restrict__ emb, float* __restrict__ out)
{
    int b = blockIdx.x;
    int t = threadIdx.x;   // 512
    __shared__ float red[512];
    float v = emb[b * 512 + t];
    red[t] = v * v;
    __syncthreads();
    for (int s = 256; s > 0; s >>= 1) {
        if (t < s) red[t] += red[t + s];
        __syncthreads();
    }
    float scale = 10.f / sqrtf(red[0] + 1e-10f);
    out[b * 512 + t] = v * scale;
}

// ---------------- launcher ----------------
extern "C" void kernel_launch(void* const* d_in, const int* in_sizes, int n_in,
                              void* d_out, int out_size)
{
    const float* input_x = (const float*)d_in[0];
    const float* conv1_w = (const float*)d_in[1];
    const float* conv1_b = (const float*)d_in[2];
    const float* bn1_g   = (const float*)d_in[3];
    const float* bn1_b   = (const float*)d_in[4];
    const float* conv2_w = (const float*)d_in[5];
    const float* conv2_b = (const float*)d_in[6];
    const float* bn2_g   = (const float*)d_in[7];
    const float* bn2_b   = (const float*)d_in[8];
    const float* conv3_w = (const float*)d_in[9];
    const float* conv3_b = (const float*)d_in[10];
    const float* bn3_g   = (const float*)d_in[11];
    const float* bn3_b   = (const float*)d_in[12];
    const float* lin4_w  = (const float*)d_in[13];
    const float* lin4_b  = (const float*)d_in[14];
    const float* bn4_g   = (const float*)d_in[15];
    const float* bn4_b   = (const float*)d_in[16];
    const float* lin5_w  = (const float*)d_in[17];
    const float* lin5_b  = (const float*)d_in[18];
    const float* bn5_g   = (const float*)d_in[19];
    const float* bn5_b   = (const float*)d_in[20];
    const float* bot_w   = (const float*)d_in[21];
    const float* bot_b   = (const float*)d_in[22];
    const float* bnb_g   = (const float*)d_in[23];
    const float* bnb_b   = (const float*)d_in[24];
    const float* emb_w   = (const float*)d_in[25];
    const float* emb_b   = (const float*)d_in[26];
    float* out = (float*)d_out;

    float *pX0, *pA, *pB, *pX5, *pM, *pZero, *pHn, *pEmb;
    float *pSc, *pSh, *pSc4, *pSh4, *pSc5, *pSh5;
    cudaGetSymbolAddress((void**)&pX0,  g_x0);
    cudaGetSymbolAddress((void**)&pA,   g_bufA);
    cudaGetSymbolAddress((void**)&pB,   g_bufB);
    cudaGetSymbolAddress((void**)&pX5,  g_x5);
    cudaGetSymbolAddress((void**)&pM,   g_M);
    cudaGetSymbolAddress((void**)&pZero,g_zero);
    cudaGetSymbolAddress((void**)&pHn,  g_hn);
    cudaGetSymbolAddress((void**)&pEmb, g_emb);
    cudaGetSymbolAddress((void**)&pSc,  g_scale);
    cudaGetSymbolAddress((void**)&pSh,  g_shift);
    cudaGetSymbolAddress((void**)&pSc4, g_scale4);
    cudaGetSymbolAddress((void**)&pSh4, g_shift4);
    cudaGetSymbolAddress((void**)&pSc5, g_scale5);
    cudaGetSymbolAddress((void**)&pSh5, g_shift5);

    transpose_kernel<<<(Bz * T0 * F0c + 255) / 256, 256>>>(input_x, pX0);

    // conv1: raw input, stats fused.  C=40,KW=5,dil=1, T 400->396, CK=200, N=6336
    conv_gemm_tf32x3<5,1,0,true><<<dim3(50, 8, 1), 256>>>(
        conv1_w, conv1_b, pX0, pA, nullptr, nullptr, nullptr, nullptr,
        40, 400, 396, 200, 6336, 0, 0, 0);
    bn_finalize<<<1, 512>>>(bn1_g, bn1_b, pSc, pSh, 1.f / 6336.f);

    // conv2: BN1 applied on load.  C=512,KW=3,dil=2, T 396->392, CK=1536, N=6272
    conv_gemm_tf32x3<3,2,1,true><<<dim3(49, 8, 1), 256>>>(
        conv2_w, conv2_b, pA, pB, nullptr, nullptr, pSc, pSh,
        512, 396, 392, 1536, 6272, 0, 0, 0);
    bn_finalize<<<1, 512>>>(bn2_g, bn2_b, pSc, pSh, 1.f / 6272.f);

    // conv3: BN2 applied on load.  C=512,KW=3,dil=4, T 392->384, CK=1536, N=6144
    conv_gemm_tf32x3<3,4,1,true><<<dim3(48, 8, 1), 256>>>(
        conv3_w, conv3_b, pB, pA, nullptr, nullptr, pSc, pSh,
        512, 392, 384, 1536, 6144, 0, 0, 0);
    bn_finalize<<<1, 512>>>(bn3_g, bn3_b, pSc, pSh, 1.f / 6144.f);

    // lin4: BN3 applied on load. pointwise 512->512, T=384, CK=512, N=6144
    conv_gemm_tf32x3<1,1,1,true><<<dim3(48, 8, 1), 256>>>(
        lin4_w, lin4_b, pA, pB, nullptr, nullptr, pSc, pSh,
        512, 384, 384, 512, 6144, 0, 0, 0);
    bn_finalize<<<1, 512>>>(bn4_g, bn4_b, pSc4, pSh4, 1.f / 6144.f);

    // lin5: BN4 applied on load (x4 raw in pB) -> x5 raw
    conv_gemm_tf32x3<1,1,1,true><<<dim3(48, 8, 1), 256>>>(
        lin5_w, lin5_b, pB, pX5, nullptr, nullptr, pSc4, pSh4,
        512, 384, 384, 512, 6144, 0, 0, 0);
    bn_finalize<<<1, 512>>>(bn5_g, bn5_b, pSc5, pSh5, 1.f / 6144.f);

    // pooling: M[b,i,j] = sum_t bn4(x4)[b,i,t]*bn5(x5)[b,j,t]
    // A = x5 raw (BN5 by row), X = x4 raw (BN4 by n). No stats.
    conv_gemm_tf32x3<1,1,2,false><<<dim3(4, 8, 16), 256>>>(
        pX5, pZero, pB, pM, pSc5, pSh5, pSc4, pSh4,
        384, 1, 1, 384, 512, Hc * T3c, Hc * T3c, Kbot);

    // bottleneck: stream 512MB of bot_w once, M-tiles staged in smem
    zero_h<<<16, 512>>>();
    bottleneck<<<dim3(16, 32), 512>>>(bot_w);

    bn2d_relu<<<1, 512>>>(bot_b, bnb_g, bnb_b);
    emb_kernel<<<16, 512>>>(pHn, emb_w, emb_b, pEmb);
    norm_kernel<<<16, 512>>>(pEmb, out);
}

// round 6
// speedup vs baseline: 1.4204x; 1.4204x over previous
#include <cuda_runtime.h>
#include <cuda_fp16.h>
#include <math.h>
#include <stdint.h>

// ---------------- problem constants ----------------
#define Bz   16
#define T0   400
#define F0c  40
#define Hc   512
#define T1c  396
#define T3c  384
#define Kbot (Hc*Hc)   // 262144

// ---------------- scratch (device globals; no allocs allowed) ----------------
__device__ float g_x0[Bz*F0c*T0];        // transposed input [B,F0,T0]
__device__ float g_bufA[Bz*Hc*T1c];      // ping
__device__ float g_bufB[Bz*Hc*T1c];      // pong
__device__ float g_x5[Bz*Hc*T3c];        // lin5 output (raw)
__device__ float g_M[Bz*Kbot];           // pooled matrices [B,512,512]
__device__ float g_sum[Hc];              // BN stat accumulators (zero-init; re-zeroed by finalize)
__device__ float g_sumsq[Hc];
__device__ float g_scale[Hc];
__device__ float g_shift[Hc];
__device__ float g_scale4[Hc];
__device__ float g_shift4[Hc];
__device__ float g_scale5[Hc];
__device__ float g_shift5[Hc];
__device__ float g_h[Bz*Hc];             // bottleneck raw accum (atomics)
__device__ float g_hn[Bz*Hc];            // post-BN h
__device__ float g_emb[Bz*Hc];
__device__ float g_zero[Hc];             // stays zero (zero-initialized)

// ---------------- helpers ----------------
// split two floats into packed fp16x2 hi word + fp16x2 lo word (x ~= hi + lo)
__device__ __forceinline__ void f16_split2(float x0, float x1, uint32_t& hw, uint32_t& lw)
{
    __half2 h = __floats2half2_rn(x0, x1);
    float2 hf = __half22float2(h);
    __half2 l = __floats2half2_rn(x0 - hf.x, x1 - hf.y);
    hw = *(uint32_t*)&h;
    lw = *(uint32_t*)&l;
}

__device__ __forceinline__ void mma_f16(float* d, uint32_t a0, uint32_t a1, uint32_t b0)
{
    asm volatile(
        "mma.sync.aligned.m16n8k8.row.col.f32.f16.f16.f32 "
        "{%0,%1,%2,%3}, {%4,%5}, {%6}, {%0,%1,%2,%3};"
        : "+f"(d[0]), "+f"(d[1]), "+f"(d[2]), "+f"(d[3])
        : "r"(a0), "r"(a1), "r"(b0));
}

__device__ __forceinline__ float relu20(float v)
{
    return fminf(fmaxf(v, 0.f), 20.f);
}

// ---------------- transpose [B,1,T,F] -> [B,F,T] ----------------
__global__ void transpose_kernel(const float* __restrict__ in, float* __restrict__ out)
{
    int idx = blockIdx.x * blockDim.x + threadIdx.x;
    if (idx >= Bz * T0 * F0c) return;
    int c = idx % F0c;
    int t = (idx / F0c) % T0;
    int b = idx / (F0c * T0);
    out[(b * F0c + c) * T0 + t] = in[idx];
}

// ---------------- FP16x3 tensor-core conv-as-GEMM, fused BN ----------------
// C[o,n] = sum_kk A[o,kk] * bnB(X[(b(n)*C + c(kk))*Tin + t(n) + kw(kk)*DIL])
// MODE 0: raw X.  MODE 1: X gets scB[c]*v+shB[c], clamp (prev-layer BN).
// MODE 2 (pooling): X gets scB[n]*v+shB[n], A gets scA[row]*v+shA[row].
// STATS: epilogue accumulates per-row sum/sumsq of (acc+bias).
// Error-compensated fp16: acc += aH*bL + aL*bH + aH*bH (lo*lo ~2^-24, dropped).
// BM=128 BN=128 BK=8 (=4 fp16x2 kpairs), 256 thr, 8 warps 2x4, warp tile 64x32,
// double-buffered smem; stride 136 (==8 mod 32) -> conflict-free LDS and STS.
#define KSTR 136
template<int KW, int DIL, int MODE, bool STATS>
__global__ __launch_bounds__(256, 2)
void conv_gemm_f16x3(const float* __restrict__ A, const float* __restrict__ bias,
                     const float* __restrict__ X, float* __restrict__ Y,
                     const float* __restrict__ scA, const float* __restrict__ shA,
                     const float* __restrict__ scB, const float* __restrict__ shB,
                     int C, int Tin, int Tout, int CK, int Ntot,
                     int strideA, int strideX, int strideY)
{
    A += (size_t)blockIdx.z * strideA;
    X += (size_t)blockIdx.z * strideX;
    Y += (size_t)blockIdx.z * strideY;

    __shared__ uint32_t AsH[2][4][KSTR];   // [buf][kpair][row]
    __shared__ uint32_t AsL[2][4][KSTR];
    __shared__ uint32_t BsH[2][4][KSTR];   // [buf][kpair][n]
    __shared__ uint32_t BsL[2][4][KSTR];
    __shared__ float sScB[Hc];
    __shared__ float sShB[Hc];

    const int tid  = threadIdx.x;
    const int lane = tid & 31;
    const int warp = tid >> 5;
    const int wm = warp >> 2;      // 0..1 (64 rows each)
    const int wn = warp & 3;       // 0..3 (32 cols each)
    const int oBase = blockIdx.y * 128;
    const int nBase = blockIdx.x * 128;

    float acc[4][4][4];
    #pragma unroll
    for (int i = 0; i < 4; i++)
        #pragma unroll
        for (int j = 0; j < 4; j++)
            #pragma unroll
            for (int r = 0; r < 4; r++) acc[i][j][r] = 0.f;

    // A loader: one float4 per thread per k8: row = tid>>1, float col = (tid&1)*4
    const int aRow = tid >> 1;
    const int aColF = (tid & 1) * 4;       // float index within k8
    const int aKp = (tid & 1) * 2;         // kpair base {0,2}
    // B loader: 4 scalars per thread per k8: n = tid&127, kk = (tid>>7)*4 + p
    const int bN  = tid & 127;
    const int bG  = tid >> 7;              // 0..1
    const int bKp = bG * 2;                // kpair base {0,2}

    const int nIdx = nBase + bN;
    const bool nValid = (nIdx < Ntot);
    int nb = 0, nt = 0;
    if (nValid) { nb = nIdx / Tout; nt = nIdx - nb * Tout; }
    const float* Xbase = X + ((size_t)nb * C) * Tin + nt;

    // per-thread BN constants for MODE 2
    float aS = 1.f, aSh = 0.f, bS = 1.f, bSh = 0.f;
    if (MODE == 2) {
        aS  = scA[oBase + aRow];
        aSh = shA[oBase + aRow];
        bS  = scB[nIdx & (Hc - 1)];
        bSh = shB[nIdx & (Hc - 1)];
    }
    if (MODE == 1) {
        for (int i = tid; i < C; i += 256) {
            sScB[i] = scB[i];
            sShB[i] = shB[i];
        }
        __syncthreads();
    }

    float pa[4], pb[4];

    // prefetch k0 = 0
    {
        const float4 av = *(const float4*)(A + (size_t)(oBase + aRow) * CK + aColF);
        pa[0] = av.x; pa[1] = av.y; pa[2] = av.z; pa[3] = av.w;
        if (MODE == 2) {
            #pragma unroll
            for (int j = 0; j < 4; j++) pa[j] = relu20(aS * pa[j] + aSh);
        }
        #pragma unroll
        for (int p = 0; p < 4; p++) {
            int kkg = bG * 4 + p;
            int c = kkg / KW;
            int kw = kkg - c * KW;
            float v = nValid ? Xbase[c * Tin + kw * DIL] : 0.f;
            if (MODE == 1) v = relu20(sScB[c] * v + sShB[c]);
            if (MODE == 2) v = relu20(bS * v + bSh);
            pb[p] = v;
        }
    }

    int pbuf = 0;
    for (int k0 = 0; k0 < CK; k0 += 8) {
        // stage current k8 tile (fp16 hi/lo split) into buffer pbuf
        {
            uint32_t h0, l0, h1, l1;
            f16_split2(pa[0], pa[1], h0, l0);
            f16_split2(pa[2], pa[3], h1, l1);
            AsH[pbuf][aKp][aRow]     = h0;  AsL[pbuf][aKp][aRow]     = l0;
            AsH[pbuf][aKp + 1][aRow] = h1;  AsL[pbuf][aKp + 1][aRow] = l1;
            f16_split2(pb[0], pb[1], h0, l0);
            f16_split2(pb[2], pb[3], h1, l1);
            BsH[pbuf][bKp][bN]     = h0;  BsL[pbuf][bKp][bN]     = l0;
            BsH[pbuf][bKp + 1][bN] = h1;  BsL[pbuf][bKp + 1][bN] = l1;
        }
        __syncthreads();

        // prefetch next k8 tile (overlaps with MMA below)
        if (k0 + 8 < CK) {
            const float4 av = *(const float4*)(A + (size_t)(oBase + aRow) * CK + k0 + 8 + aColF);
            pa[0] = av.x; pa[1] = av.y; pa[2] = av.z; pa[3] = av.w;
            if (MODE == 2) {
                #pragma unroll
                for (int j = 0; j < 4; j++) pa[j] = relu20(aS * pa[j] + aSh);
            }
            #pragma unroll
            for (int p = 0; p < 4; p++) {
                int kkg = k0 + 8 + bG * 4 + p;
                int c = kkg / KW;
                int kw = kkg - c * KW;
                float v = nValid ? Xbase[c * Tin + kw * DIL] : 0.f;
                if (MODE == 1) v = relu20(sScB[c] * v + sShB[c]);
                if (MODE == 2) v = relu20(bS * v + bSh);
                pb[p] = v;
            }
        }

        // fragments; banks = 8*kpair + idx -> conflict-free
        const int kk = lane & 3;
        const int rsub = lane >> 2;
        uint32_t aH[4][2], aL[4][2];
        #pragma unroll
        for (int mt = 0; mt < 4; mt++) {
            int row = wm * 64 + mt * 16 + rsub;
            aH[mt][0] = AsH[pbuf][kk][row];     aL[mt][0] = AsL[pbuf][kk][row];
            aH[mt][1] = AsH[pbuf][kk][row + 8]; aL[mt][1] = AsL[pbuf][kk][row + 8];
        }
        uint32_t bH[4], bL[4];
        #pragma unroll
        for (int ntile = 0; ntile < 4; ntile++) {
            int col = wn * 32 + ntile * 8 + rsub;
            bH[ntile] = BsH[pbuf][kk][col];
            bL[ntile] = BsL[pbuf][kk][col];
        }
        #pragma unroll
        for (int mt = 0; mt < 4; mt++)
            #pragma unroll
            for (int ntile = 0; ntile < 4; ntile++) {
                mma_f16(acc[mt][ntile], aH[mt][0], aH[mt][1], bL[ntile]);
                mma_f16(acc[mt][ntile], aL[mt][0], aL[mt][1], bH[ntile]);
                mma_f16(acc[mt][ntile], aH[mt][0], aH[mt][1], bH[ntile]);
            }

        pbuf ^= 1;
    }

    // epilogue: D[row, col] -> Y[(b*Hc + o)*Tout + t] + bias[o]; optional BN stats
    #pragma unroll
    for (int mt = 0; mt < 4; mt++) {
        int row0 = oBase + wm * 64 + mt * 16 + (lane >> 2);
        float b0 = bias[row0];
        float b1 = bias[row0 + 8];
        float s0 = 0.f, q0 = 0.f, s1 = 0.f, q1 = 0.f;
        #pragma unroll
        for (int ntile = 0; ntile < 4; ntile++) {
            int col0 = nBase + wn * 32 + ntile * 8 + (lane & 3) * 2;
            #pragma unroll
            for (int cc = 0; cc < 2; cc++) {
                int col = col0 + cc;
                if (col < Ntot) {
                    float v0 = acc[mt][ntile][cc]     + b0;
                    float v1 = acc[mt][ntile][2 + cc] + b1;
                    int b = col / Tout;
                    int t = col - b * Tout;
                    size_t base = ((size_t)b * Hc) * Tout + t;
                    Y[base + (size_t)row0 * Tout]       = v0;
                    Y[base + (size_t)(row0 + 8) * Tout] = v1;
                    if (STATS) {
                        s0 += v0; q0 += v0 * v0;
                        s1 += v1; q1 += v1 * v1;
                    }
                }
            }
        }
        if (STATS) {
            #pragma unroll
            for (int off = 2; off >= 1; off >>= 1) {
                s0 += __shfl_down_sync(0xffffffffu, s0, off);
                q0 += __shfl_down_sync(0xffffffffu, q0, off);
                s1 += __shfl_down_sync(0xffffffffu, s1, off);
                q1 += __shfl_down_sync(0xffffffffu, q1, off);
            }
            if ((lane & 3) == 0) {
                atomicAdd(&g_sum[row0], s0);
                atomicAdd(&g_sumsq[row0], q0);
                atomicAdd(&g_sum[row0 + 8], s1);
                atomicAdd(&g_sumsq[row0 + 8], q1);
            }
        }
    }
}

// ---------------- BN finalize: sums -> scale/shift; re-zero accumulators ----------------
__global__ void bn_finalize(const float* __restrict__ g, const float* __restrict__ be,
                            float* __restrict__ sc, float* __restrict__ sh, float invN)
{
    int c = threadIdx.x;   // 512
    float s = g_sum[c], q = g_sumsq[c];
    float m = s * invN;
    float var = q * invN - m * m;
    float a = g[c] * rsqrtf(var + 1e-5f);
    sc[c] = a;
    sh[c] = be[c] - a * m;
    g_sum[c] = 0.f;
    g_sumsq[c] = 0.f;
}

// ---------------- bottleneck: h[b,o] += sum_k M[b,k]*W[o,k] ----------------
__global__ void zero_h()
{
    g_h[blockIdx.x * blockDim.x + threadIdx.x] = 0.f;
}

__global__ __launch_bounds__(512)
void bottleneck(const float* __restrict__ W)
{
    __shared__ float Ms[Bz][512];
    int warp = threadIdx.x >> 5, lane = threadIdx.x & 31;
    int o0 = blockIdx.x * 32 + warp * 2;           // 16 warps x 2 o each
    int k0 = blockIdx.y * (Kbot / 32);             // 8192-wide K split

    float acc0[16], acc1[16];
    #pragma unroll
    for (int b = 0; b < 16; b++) { acc0[b] = 0.f; acc1[b] = 0.f; }

    for (int kt = 0; kt < Kbot / 32; kt += 512) {
        __syncthreads();
        #pragma unroll
        for (int i = 0; i < 16; i++) {
            int idx = threadIdx.x + i * 512;
            int b = idx >> 9, kk = idx & 511;
            Ms[b][kk] = g_M[b * Kbot + k0 + kt + kk];
        }
        __syncthreads();
        const float* w0p = W + (size_t)o0 * Kbot + k0 + kt;
        const float* w1p = w0p + Kbot;
        #pragma unroll
        for (int kk = lane * 4; kk < 512; kk += 128) {
            float4 w0 = *(const float4*)(w0p + kk);
            float4 w1 = *(const float4*)(w1p + kk);
            #pragma unroll
            for (int b = 0; b < 16; b++) {
                float4 m = *(const float4*)&Ms[b][kk];
                acc0[b] += w0.x * m.x + w0.y * m.y + w0.z * m.z + w0.w * m.w;
                acc1[b] += w1.x * m.x + w1.y * m.y + w1.z * m.z + w1.w * m.w;
            }
        }
    }
    #pragma unroll
    for (int b = 0; b < 16; b++) {
        float v0 = acc0[b], v1 = acc1[b];
        #pragma unroll
        for (int off = 16; off; off >>= 1) {
            v0 += __shfl_down_sync(0xffffffffu, v0, off);
            v1 += __shfl_down_sync(0xffffffffu, v1, off);
        }
        if (lane == 0) {
            atomicAdd(&g_h[b * Hc + o0], v0);
            atomicAdd(&g_h[b * Hc + o0 + 1], v1);
        }
    }
}

// ---------------- BN over batch dim (16 samples) + relu20 ----------------
__global__ void bn2d_relu(const float* __restrict__ bot_b, const float* __restrict__ gg,
                          const float* __restrict__ gb)
{
    int o = threadIdx.x;   // 512 threads
    float v[16];
    float s = 0.f, sq = 0.f;
    #pragma unroll
    for (int b = 0; b < 16; b++) {
        float x = g_h[b * Hc + o] + bot_b[o];
        v[b] = x; s += x; sq += x * x;
    }
    float m = s * (1.f / 16.f);
    float var = sq * (1.f / 16.f) - m * m;
    float a = gg[o] * rsqrtf(var + 1e-5f);
    float d = gb[o] - a * m;
    #pragma unroll
    for (int b = 0; b < 16; b++) {
        float z = a * v[b] + d;
        g_hn[b * Hc + o] = fminf(fmaxf(z, 0.f), 20.f);
    }
}

// ---------------- embedding GEMV + bias ----------------
__global__ void emb_kernel(const float* __restrict__ h, const float* __restrict__ W,
                           const float* __restrict__ bias, float* __restrict__ emb)
{
    int b = blockIdx.x;
    int warp = threadIdx.x >> 5, lane = threadIdx.x & 31;
    __shared__ float hs[512];
    hs[threadIdx.x] = h[b * Hc + threadIdx.x];
    __syncthreads();
    for (int e = warp; e < 512; e += 16) {
        float s = 0.f;
        for (int c = lane; c < 512; c += 32)
            s += hs[c] * W[e * 512 + c];
        #pragma unroll
        for (int off = 16; off; off >>= 1)
            s += __shfl_down_sync(0xffffffffu, s, off);
        if (lane == 0) emb[b * Hc + e] = s + bias[e];
    }
}

// ---------------- L2 normalize * 10 ----------------
__global__ void norm_kernel(const float* __restrict__ emb, float* __restrict__ out)
{
    int b = blockIdx.x;
    int t = threadIdx.x;   // 512
    __shared__ float red[512];
    float v = emb[b * 512 + t];
    red[t] = v * v;
    __syncthreads();
    for (int s = 256; s > 0; s >>= 1) {
        if (t < s) red[t] += red[t + s];
        __syncthreads();
    }
    float scale = 10.f / sqrtf(red[0] + 1e-10f);
    out[b * 512 + t] = v * scale;
}

// ---------------- launcher ----------------
extern "C" void kernel_launch(void* const* d_in, const int* in_sizes, int n_in,
                              void* d_out, int out_size)
{
    const float* input_x = (const float*)d_in[0];
    const float* conv1_w = (const float*)d_in[1];
    const float* conv1_b = (const float*)d_in[2];
    const float* bn1_g   = (const float*)d_in[3];
    const float* bn1_b   = (const float*)d_in[4];
    const float* conv2_w = (const float*)d_in[5];
    const float* conv2_b = (const float*)d_in[6];
    const float* bn2_g   = (const float*)d_in[7];
    const float* bn2_b   = (const float*)d_in[8];
    const float* conv3_w = (const float*)d_in[9];
    const float* conv3_b = (const float*)d_in[10];
    const float* bn3_g   = (const float*)d_in[11];
    const float* bn3_b   = (const float*)d_in[12];
    const float* lin4_w  = (const float*)d_in[13];
    const float* lin4_b  = (const float*)d_in[14];
    const float* bn4_g   = (const float*)d_in[15];
    const float* bn4_b   = (const float*)d_in[16];
    const float* lin5_w  = (const float*)d_in[17];
    const float* lin5_b  = (const float*)d_in[18];
    const float* bn5_g   = (const float*)d_in[19];
    const float* bn5_b   = (const float*)d_in[20];
    const float* bot_w   = (const float*)d_in[21];
    const float* bot_b   = (const float*)d_in[22];
    const float* bnb_g   = (const float*)d_in[23];
    const float* bnb_b   = (const float*)d_in[24];
    const float* emb_w   = (const float*)d_in[25];
    const float* emb_b   = (const float*)d_in[26];
    float* out = (float*)d_out;

    float *pX0, *pA, *pB, *pX5, *pM, *pZero, *pHn, *pEmb;
    float *pSc, *pSh, *pSc4, *pSh4, *pSc5, *pSh5;
    cudaGetSymbolAddress((void**)&pX0,  g_x0);
    cudaGetSymbolAddress((void**)&pA,   g_bufA);
    cudaGetSymbolAddress((void**)&pB,   g_bufB);
    cudaGetSymbolAddress((void**)&pX5,  g_x5);
    cudaGetSymbolAddress((void**)&pM,   g_M);
    cudaGetSymbolAddress((void**)&pZero,g_zero);
    cudaGetSymbolAddress((void**)&pHn,  g_hn);
    cudaGetSymbolAddress((void**)&pEmb, g_emb);
    cudaGetSymbolAddress((void**)&pSc,  g_scale);
    cudaGetSymbolAddress((void**)&pSh,  g_shift);
    cudaGetSymbolAddress((void**)&pSc4, g_scale4);
    cudaGetSymbolAddress((void**)&pSh4, g_shift4);
    cudaGetSymbolAddress((void**)&pSc5, g_scale5);
    cudaGetSymbolAddress((void**)&pSh5, g_shift5);

    transpose_kernel<<<(Bz * T0 * F0c + 255) / 256, 256>>>(input_x, pX0);

    // conv1: raw input, stats fused.  C=40,KW=5,dil=1, T 400->396, CK=200, N=6336
    conv_gemm_f16x3<5,1,0,true><<<dim3(50, 4, 1), 256>>>(
        conv1_w, conv1_b, pX0, pA, nullptr, nullptr, nullptr, nullptr,
        40, 400, 396, 200, 6336, 0, 0, 0);
    bn_finalize<<<1, 512>>>(bn1_g, bn1_b, pSc, pSh, 1.f / 6336.f);

    // conv2: BN1 applied on load.  C=512,KW=3,dil=2, T 396->392, CK=1536, N=6272
    conv_gemm_f16x3<3,2,1,true><<<dim3(49, 4, 1), 256>>>(
        conv2_w, conv2_b, pA, pB, nullptr, nullptr, pSc, pSh,
        512, 396, 392, 1536, 6272, 0, 0, 0);
    bn_finalize<<<1, 512>>>(bn2_g, bn2_b, pSc, pSh, 1.f / 6272.f);

    // conv3: BN2 applied on load.  C=512,KW=3,dil=4, T 392->384, CK=1536, N=6144
    conv_gemm_f16x3<3,4,1,true><<<dim3(48, 4, 1), 256>>>(
        conv3_w, conv3_b, pB, pA, nullptr, nullptr, pSc, pSh,
        512, 392, 384, 1536, 6144, 0, 0, 0);
    bn_finalize<<<1, 512>>>(bn3_g, bn3_b, pSc, pSh, 1.f / 6144.f);

    // lin4: BN3 applied on load. pointwise 512->512, T=384, CK=512, N=6144
    conv_gemm_f16x3<1,1,1,true><<<dim3(48, 4, 1), 256>>>(
        lin4_w, lin4_b, pA, pB, nullptr, nullptr, pSc, pSh,
        512, 384, 384, 512, 6144, 0, 0, 0);
    bn_finalize<<<1, 512>>>(bn4_g, bn4_b, pSc4, pSh4, 1.f / 6144.f);

    // lin5: BN4 applied on load (x4 raw in pB) -> x5 raw
    conv_gemm_f16x3<1,1,1,true><<<dim3(48, 4, 1), 256>>>(
        lin5_w, lin5_b, pB, pX5, nullptr, nullptr, pSc4, pSh4,
        512, 384, 384, 512, 6144, 0, 0, 0);
    bn_finalize<<<1, 512>>>(bn5_g, bn5_b, pSc5, pSh5, 1.f / 6144.f);

    // pooling: M[b,i,j] = sum_t bn4(x4)[b,i,t]*bn5(x5)[b,j,t]
    // A = x5 raw (BN5 by row), X = x4 raw (BN4 by n). No stats.
    conv_gemm_f16x3<1,1,2,false><<<dim3(4, 4, 16), 256>>>(
        pX5, pZero, pB, pM, pSc5, pSh5, pSc4, pSh4,
        384, 1, 1, 384, 512, Hc * T3c, Hc * T3c, Kbot);

    // bottleneck: stream 512MB of bot_w once, M-tiles staged in smem
    zero_h<<<16, 512>>>();
    bottleneck<<<dim3(16, 32), 512>>>(bot_w);

    bn2d_relu<<<1, 512>>>(bot_b, bnb_g, bnb_b);
    emb_kernel<<<16, 512>>>(pHn, emb_w, emb_b, pEmb);
    norm_kernel<<<16, 512>>>(pEmb, out);
}

// round 7
// speedup vs baseline: 1.6610x; 1.1694x over previous
#include <cuda_runtime.h>
#include <cuda_fp16.h>
#include <math.h>
#include <stdint.h>

// ---------------- problem constants ----------------
#define Bz   16
#define T0   400
#define F0c  40
#define Hc   512
#define T1c  396
#define T3c  384
#define Kbot (Hc*Hc)   // 262144

// ---------------- scratch (device globals; no allocs allowed) ----------------
__device__ float g_x0[Bz*F0c*T0];        // transposed input [B,F0,T0]
__device__ float g_bufA[Bz*Hc*T1c];      // ping
__device__ float g_bufB[Bz*Hc*T1c];      // pong
__device__ float g_x5[Bz*Hc*T3c];        // lin5 output (raw)
__device__ float g_M[Bz*Kbot];           // pooled matrices [B,512,512]
__device__ float g_sum[Hc];              // BN stat accumulators (zero-init; re-zeroed by finalize)
__device__ float g_sumsq[Hc];
__device__ float g_scale[Hc];
__device__ float g_shift[Hc];
__device__ float g_scale4[Hc];
__device__ float g_shift4[Hc];
__device__ float g_scale5[Hc];
__device__ float g_shift5[Hc];
__device__ float g_h[Bz*Hc];             // bottleneck raw accum (atomics)
__device__ float g_hn[Bz*Hc];            // post-BN h
__device__ float g_emb[Bz*Hc];
__device__ float g_zero[Hc];             // stays zero (zero-initialized)

// ---------------- helpers ----------------
// split two floats into packed fp16x2 hi word + fp16x2 lo word (x ~= hi + lo)
__device__ __forceinline__ void f16_split2(float x0, float x1, uint32_t& hw, uint32_t& lw)
{
    __half2 h = __floats2half2_rn(x0, x1);
    float2 hf = __half22float2(h);
    __half2 l = __floats2half2_rn(x0 - hf.x, x1 - hf.y);
    hw = *(uint32_t*)&h;
    lw = *(uint32_t*)&l;
}

__device__ __forceinline__ void mma_f16_k16(float* d, const uint32_t* a, const uint32_t* b)
{
    asm volatile(
        "mma.sync.aligned.m16n8k16.row.col.f32.f16.f16.f32 "
        "{%0,%1,%2,%3}, {%4,%5,%6,%7}, {%8,%9}, {%0,%1,%2,%3};"
        : "+f"(d[0]), "+f"(d[1]), "+f"(d[2]), "+f"(d[3])
        : "r"(a[0]), "r"(a[1]), "r"(a[2]), "r"(a[3]), "r"(b[0]), "r"(b[1]));
}

__device__ __forceinline__ float relu20(float v)
{
    return fminf(fmaxf(v, 0.f), 20.f);
}

// ---------------- transpose [B,1,T,F] -> [B,F,T] ----------------
__global__ void transpose_kernel(const float* __restrict__ in, float* __restrict__ out)
{
    int idx = blockIdx.x * blockDim.x + threadIdx.x;
    if (idx >= Bz * T0 * F0c) return;
    int c = idx % F0c;
    int t = (idx / F0c) % T0;
    int b = idx / (F0c * T0);
    out[(b * F0c + c) * T0 + t] = in[idx];
}

// ---------------- FP16x3 tensor-core conv-as-GEMM (k16), fused BN ----------------
// C[o,n] = sum_kk A[o,kk] * bnB(X[(b(n)*C + c(kk))*Tin + t(n) + kw(kk)*DIL])
// MODE 0: raw X.  MODE 1: X gets scB[c]*v+shB[c], clamp.  MODE 2 (pooling): both sides BN'd.
// STATS: epilogue accumulates per-row sum/sumsq of (acc+bias).
// Error-compensated fp16: acc += aH*bL + aL*bH + aH*bH.
// BM=128 BN=64 BK=16 (8 fp16x2 kpairs), 256 thr, 8 warps 2x4, warp tile 64x16,
// mma.m16n8k16, double-buffered smem; strides 136/72 (==8 mod 32) conflict-free.
#define ASTR 136
#define BSTR 72
template<int KW, int DIL, int MODE, bool STATS>
__global__ __launch_bounds__(256, 3)
void conv_gemm_f16k16(const float* __restrict__ A, const float* __restrict__ bias,
                      const float* __restrict__ X, float* __restrict__ Y,
                      const float* __restrict__ scA, const float* __restrict__ shA,
                      const float* __restrict__ scB, const float* __restrict__ shB,
                      int C, int Tin, int Tout, int CK, int Ntot,
                      int strideA, int strideX, int strideY)
{
    A += (size_t)blockIdx.z * strideA;
    X += (size_t)blockIdx.z * strideX;
    Y += (size_t)blockIdx.z * strideY;

    __shared__ uint32_t AsH[2][8][ASTR];   // [buf][kpair][row]
    __shared__ uint32_t AsL[2][8][ASTR];
    __shared__ uint32_t BsH[2][8][BSTR];   // [buf][kpair][n]
    __shared__ uint32_t BsL[2][8][BSTR];
    __shared__ float sScB[Hc];
    __shared__ float sShB[Hc];

    const int tid  = threadIdx.x;
    const int lane = tid & 31;
    const int warp = tid >> 5;
    const int wm = warp >> 2;      // 0..1 (64 rows each)
    const int wn = warp & 3;       // 0..3 (16 cols each)
    const int oBase = blockIdx.y * 128;
    const int nBase = blockIdx.x * 64;

    float acc[4][2][4];
    #pragma unroll
    for (int i = 0; i < 4; i++)
        #pragma unroll
        for (int j = 0; j < 2; j++)
            #pragma unroll
            for (int r = 0; r < 4; r++) acc[i][j][r] = 0.f;

    // A loader: 128 rows x 16 floats / 256 thr = 8 floats = 2 float4 per thread.
    // row = tid>>1; even/odd threads take float cols {0-3,8-11} / {4-7,12-15}
    // -> kpairs {0,1,4,5} / {2,3,6,7}  (interleave keeps STS conflict-free)
    const int aRow = tid >> 1;
    const int aC0  = (tid & 1) * 4;    // first float4 col
    const int aKp  = (tid & 1) * 2;    // kpair base (second group at +4)
    // B loader: 16 k x 64 n / 256 thr = 4 scalars: n = tid&63, k = (tid>>6)*4 + p
    const int bN  = tid & 63;
    const int bG  = tid >> 6;          // 0..3
    const int bKp = bG * 2;

    const int nIdx = nBase + bN;
    const bool nValid = (nIdx < Ntot);
    int nb = 0, nt0 = 0;
    if (nValid) { nb = nIdx / Tout; nt0 = nIdx - nb * Tout; }
    const float* Xbase = X + ((size_t)nb * C) * Tin + nt0;
    const float* Arow = A + (size_t)(oBase + aRow) * CK;

    // per-thread BN constants for MODE 2
    float aS = 1.f, aSh = 0.f, bS = 1.f, bSh = 0.f;
    if (MODE == 2) {
        aS  = scA[oBase + aRow];
        aSh = shA[oBase + aRow];
        bS  = scB[nIdx & (Hc - 1)];
        bSh = shB[nIdx & (Hc - 1)];
    }
    if (MODE == 1) {
        for (int i = tid; i < C; i += 256) {
            sScB[i] = scB[i];
            sShB[i] = shB[i];
        }
        __syncthreads();
    }

    float pa[8], pb[4];

    // ---- prefetch k0 = 0 ----
    {
        const float4 av = *(const float4*)(Arow + aC0);
        pa[0] = av.x; pa[1] = av.y; pa[2] = av.z; pa[3] = av.w;
        if (aC0 + 11 < CK) {
            const float4 av2 = *(const float4*)(Arow + aC0 + 8);
            pa[4] = av2.x; pa[5] = av2.y; pa[6] = av2.z; pa[7] = av2.w;
        } else {
            pa[4] = pa[5] = pa[6] = pa[7] = 0.f;
        }
        if (MODE == 2) {
            #pragma unroll
            for (int j = 0; j < 8; j++) pa[j] = relu20(aS * pa[j] + aSh);
        }
        #pragma unroll
        for (int p = 0; p < 4; p++) {
            int kkg = bG * 4 + p;
            float v = 0.f;
            if (nValid && kkg < CK) {
                int c = kkg / KW;
                int kw = kkg - c * KW;
                v = Xbase[c * Tin + kw * DIL];
                if (MODE == 1) v = relu20(sScB[c] * v + sShB[c]);
                if (MODE == 2) v = relu20(bS * v + bSh);
            }
            pb[p] = v;
        }
    }

    const int nSteps = (CK + 15) >> 4;
    int pbuf = 0;
    for (int s = 0; s < nSteps; s++) {
        // stage current k16 tile (fp16 hi/lo split)
        {
            uint32_t h, l;
            f16_split2(pa[0], pa[1], h, l); AsH[pbuf][aKp][aRow]     = h; AsL[pbuf][aKp][aRow]     = l;
            f16_split2(pa[2], pa[3], h, l); AsH[pbuf][aKp + 1][aRow] = h; AsL[pbuf][aKp + 1][aRow] = l;
            f16_split2(pa[4], pa[5], h, l); AsH[pbuf][aKp + 4][aRow] = h; AsL[pbuf][aKp + 4][aRow] = l;
            f16_split2(pa[6], pa[7], h, l); AsH[pbuf][aKp + 5][aRow] = h; AsL[pbuf][aKp + 5][aRow] = l;
            f16_split2(pb[0], pb[1], h, l); BsH[pbuf][bKp][bN]     = h; BsL[pbuf][bKp][bN]     = l;
            f16_split2(pb[2], pb[3], h, l); BsH[pbuf][bKp + 1][bN] = h; BsL[pbuf][bKp + 1][bN] = l;
        }
        __syncthreads();

        // prefetch next k16 tile
        if (s + 1 < nSteps) {
            int k0 = (s + 1) * 16;
            const float4 av = *(const float4*)(Arow + k0 + aC0);
            pa[0] = av.x; pa[1] = av.y; pa[2] = av.z; pa[3] = av.w;
            if (k0 + aC0 + 11 < CK) {
                const float4 av2 = *(const float4*)(Arow + k0 + aC0 + 8);
                pa[4] = av2.x; pa[5] = av2.y; pa[6] = av2.z; pa[7] = av2.w;
            } else {
                pa[4] = pa[5] = pa[6] = pa[7] = 0.f;
            }
            if (MODE == 2) {
                #pragma unroll
                for (int j = 0; j < 8; j++) pa[j] = relu20(aS * pa[j] + aSh);
            }
            #pragma unroll
            for (int p = 0; p < 4; p++) {
                int kkg = k0 + bG * 4 + p;
                float v = 0.f;
                if (nValid && kkg < CK) {
                    int c = kkg / KW;
                    int kw = kkg - c * KW;
                    v = Xbase[c * Tin + kw * DIL];
                    if (MODE == 1) v = relu20(sScB[c] * v + sShB[c]);
                    if (MODE == 2) v = relu20(bS * v + bSh);
                }
                pb[p] = v;
            }
        }

        // fragments; banks = 8*kpair + idx -> conflict-free
        const int kk = lane & 3;
        const int rsub = lane >> 2;
        uint32_t bHf[2][2], bLf[2][2];
        #pragma unroll
        for (int nt = 0; nt < 2; nt++) {
            int col = wn * 16 + nt * 8 + rsub;
            bHf[nt][0] = BsH[pbuf][kk][col];     bLf[nt][0] = BsL[pbuf][kk][col];
            bHf[nt][1] = BsH[pbuf][kk + 4][col]; bLf[nt][1] = BsL[pbuf][kk + 4][col];
        }
        #pragma unroll
        for (int mt = 0; mt < 4; mt++) {
            int row = wm * 64 + mt * 16 + rsub;
            uint32_t aHf[4], aLf[4];
            aHf[0] = AsH[pbuf][kk][row];     aLf[0] = AsL[pbuf][kk][row];
            aHf[1] = AsH[pbuf][kk][row + 8]; aLf[1] = AsL[pbuf][kk][row + 8];
            aHf[2] = AsH[pbuf][kk + 4][row];     aLf[2] = AsL[pbuf][kk + 4][row];
            aHf[3] = AsH[pbuf][kk + 4][row + 8]; aLf[3] = AsL[pbuf][kk + 4][row + 8];
            #pragma unroll
            for (int nt = 0; nt < 2; nt++) {
                mma_f16_k16(acc[mt][nt], aHf, bLf[nt]);
                mma_f16_k16(acc[mt][nt], aLf, bHf[nt]);
                mma_f16_k16(acc[mt][nt], aHf, bHf[nt]);
            }
        }

        pbuf ^= 1;
    }

    // epilogue: D[row, col] -> Y[(b*Hc + o)*Tout + t] + bias[o]; optional BN stats
    #pragma unroll
    for (int mt = 0; mt < 4; mt++) {
        int row0 = oBase + wm * 64 + mt * 16 + (lane >> 2);
        float b0 = bias[row0];
        float b1 = bias[row0 + 8];
        float s0 = 0.f, q0 = 0.f, s1 = 0.f, q1 = 0.f;
        #pragma unroll
        for (int nt = 0; nt < 2; nt++) {
            int col0 = nBase + wn * 16 + nt * 8 + (lane & 3) * 2;
            #pragma unroll
            for (int cc = 0; cc < 2; cc++) {
                int col = col0 + cc;
                if (col < Ntot) {
                    float v0 = acc[mt][nt][cc]     + b0;
                    float v1 = acc[mt][nt][2 + cc] + b1;
                    int b = col / Tout;
                    int t = col - b * Tout;
                    size_t base = ((size_t)b * Hc) * Tout + t;
                    Y[base + (size_t)row0 * Tout]       = v0;
                    Y[base + (size_t)(row0 + 8) * Tout] = v1;
                    if (STATS) {
                        s0 += v0; q0 += v0 * v0;
                        s1 += v1; q1 += v1 * v1;
                    }
                }
            }
        }
        if (STATS) {
            #pragma unroll
            for (int off = 2; off >= 1; off >>= 1) {
                s0 += __shfl_down_sync(0xffffffffu, s0, off);
                q0 += __shfl_down_sync(0xffffffffu, q0, off);
                s1 += __shfl_down_sync(0xffffffffu, s1, off);
                q1 += __shfl_down_sync(0xffffffffu, q1, off);
            }
            if ((lane & 3) == 0) {
                atomicAdd(&g_sum[row0], s0);
                atomicAdd(&g_sumsq[row0], q0);
                atomicAdd(&g_sum[row0 + 8], s1);
                atomicAdd(&g_sumsq[row0 + 8], q1);
            }
        }
    }
}

// ---------------- BN finalize: sums -> scale/shift; re-zero accumulators ----------------
__global__ void bn_finalize(const float* __restrict__ g, const float* __restrict__ be,
                            float* __restrict__ sc, float* __restrict__ sh, float invN)
{
    int c = threadIdx.x;   // 512
    float s = g_sum[c], q = g_sumsq[c];
    float m = s * invN;
    float var = q * invN - m * m;
    float a = g[c] * rsqrtf(var + 1e-5f);
    sc[c] = a;
    sh[c] = be[c] - a * m;
    g_sum[c] = 0.f;
    g_sumsq[c] = 0.f;
}

// ---------------- bottleneck: h[b,o] += sum_k M[b,k]*W[o,k] ----------------
__global__ void zero_h()
{
    g_h[blockIdx.x * blockDim.x + threadIdx.x] = 0.f;
}

__global__ __launch_bounds__(512)
void bottleneck(const float* __restrict__ W)
{
    __shared__ float Ms[Bz][512];
    int warp = threadIdx.x >> 5, lane = threadIdx.x & 31;
    int o0 = blockIdx.x * 32 + warp * 2;           // 16 warps x 2 o each
    int k0 = blockIdx.y * (Kbot / 32);             // 8192-wide K split

    float acc0[16], acc1[16];
    #pragma unroll
    for (int b = 0; b < 16; b++) { acc0[b] = 0.f; acc1[b] = 0.f; }

    for (int kt = 0; kt < Kbot / 32; kt += 512) {
        __syncthreads();
        #pragma unroll
        for (int i = 0; i < 16; i++) {
            int idx = threadIdx.x + i * 512;
            int b = idx >> 9, kk = idx & 511;
            Ms[b][kk] = g_M[b * Kbot + k0 + kt + kk];
        }
        __syncthreads();
        const float* w0p = W + (size_t)o0 * Kbot + k0 + kt;
        const float* w1p = w0p + Kbot;
        #pragma unroll
        for (int kk = lane * 4; kk < 512; kk += 128) {
            float4 w0 = *(const float4*)(w0p + kk);
            float4 w1 = *(const float4*)(w1p + kk);
            #pragma unroll
            for (int b = 0; b < 16; b++) {
                float4 m = *(const float4*)&Ms[b][kk];
                acc0[b] += w0.x * m.x + w0.y * m.y + w0.z * m.z + w0.w * m.w;
                acc1[b] += w1.x * m.x + w1.y * m.y + w1.z * m.z + w1.w * m.w;
            }
        }
    }
    #pragma unroll
    for (int b = 0; b < 16; b++) {
        float v0 = acc0[b], v1 = acc1[b];
        #pragma unroll
        for (int off = 16; off; off >>= 1) {
            v0 += __shfl_down_sync(0xffffffffu, v0, off);
            v1 += __shfl_down_sync(0xffffffffu, v1, off);
        }
        if (lane == 0) {
            atomicAdd(&g_h[b * Hc + o0], v0);
            atomicAdd(&g_h[b * Hc + o0 + 1], v1);
        }
    }
}

// ---------------- BN over batch dim (16 samples) + relu20 ----------------
__global__ void bn2d_relu(const float* __restrict__ bot_b, const float* __restrict__ gg,
                          const float* __restrict__ gb)
{
    int o = threadIdx.x;   // 512 threads
    float v[16];
    float s = 0.f, sq = 0.f;
    #pragma unroll
    for (int b = 0; b < 16; b++) {
        float x = g_h[b * Hc + o] + bot_b[o];
        v[b] = x; s += x; sq += x * x;
    }
    float m = s * (1.f / 16.f);
    float var = sq * (1.f / 16.f) - m * m;
    float a = gg[o] * rsqrtf(var + 1e-5f);
    float d = gb[o] - a * m;
    #pragma unroll
    for (int b = 0; b < 16; b++) {
        float z = a * v[b] + d;
        g_hn[b * Hc + o] = fminf(fmaxf(z, 0.f), 20.f);
    }
}

// ---------------- embedding GEMV + bias ----------------
__global__ void emb_kernel(const float* __restrict__ h, const float* __restrict__ W,
                           const float* __restrict__ bias, float* __restrict__ emb)
{
    int b = blockIdx.x;
    int warp = threadIdx.x >> 5, lane = threadIdx.x & 31;
    __shared__ float hs[512];
    hs[threadIdx.x] = h[b * Hc + threadIdx.x];
    __syncthreads();
    for (int e = warp; e < 512; e += 16) {
        float s = 0.f;
        for (int c = lane; c < 512; c += 32)
            s += hs[c] * W[e * 512 + c];
        #pragma unroll
        for (int off = 16; off; off >>= 1)
            s += __shfl_down_sync(0xffffffffu, s, off);
        if (lane == 0) emb[b * Hc + e] = s + bias[e];
    }
}

// ---------------- L2 normalize * 10 ----------------
__global__ void norm_kernel(const float* __restrict__ emb, float* __restrict__ out)
{
    int b = blockIdx.x;
    int t = threadIdx.x;   // 512
    __shared__ float red[512];
    float v = emb[b * 512 + t];
    red[t] = v * v;
    __syncthreads();
    for (int s = 256; s > 0; s >>= 1) {
        if (t < s) red[t] += red[t + s];
        __syncthreads();
    }
    float scale = 10.f / sqrtf(red[0] + 1e-10f);
    out[b * 512 + t] = v * scale;
}

// ---------------- launcher ----------------
extern "C" void kernel_launch(void* const* d_in, const int* in_sizes, int n_in,
                              void* d_out, int out_size)
{
    const float* input_x = (const float*)d_in[0];
    const float* conv1_w = (const float*)d_in[1];
    const float* conv1_b = (const float*)d_in[2];
    const float* bn1_g   = (const float*)d_in[3];
    const float* bn1_b   = (const float*)d_in[4];
    const float* conv2_w = (const float*)d_in[5];
    const float* conv2_b = (const float*)d_in[6];
    const float* bn2_g   = (const float*)d_in[7];
    const float* bn2_b   = (const float*)d_in[8];
    const float* conv3_w = (const float*)d_in[9];
    const float* conv3_b = (const float*)d_in[10];
    const float* bn3_g   = (const float*)d_in[11];
    const float* bn3_b   = (const float*)d_in[12];
    const float* lin4_w  = (const float*)d_in[13];
    const float* lin4_b  = (const float*)d_in[14];
    const float* bn4_g   = (const float*)d_in[15];
    const float* bn4_b   = (const float*)d_in[16];
    const float* lin5_w  = (const float*)d_in[17];
    const float* lin5_b  = (const float*)d_in[18];
    const float* bn5_g   = (const float*)d_in[19];
    const float* bn5_b   = (const float*)d_in[20];
    const float* bot_w   = (const float*)d_in[21];
    const float* bot_b   = (const float*)d_in[22];
    const float* bnb_g   = (const float*)d_in[23];
    const float* bnb_b   = (const float*)d_in[24];
    const float* emb_w   = (const float*)d_in[25];
    const float* emb_b   = (const float*)d_in[26];
    float* out = (float*)d_out;

    float *pX0, *pA, *pB, *pX5, *pM, *pZero, *pHn, *pEmb;
    float *pSc, *pSh, *pSc4, *pSh4, *pSc5, *pSh5;
    cudaGetSymbolAddress((void**)&pX0,  g_x0);
    cudaGetSymbolAddress((void**)&pA,   g_bufA);
    cudaGetSymbolAddress((void**)&pB,   g_bufB);
    cudaGetSymbolAddress((void**)&pX5,  g_x5);
    cudaGetSymbolAddress((void**)&pM,   g_M);
    cudaGetSymbolAddress((void**)&pZero,g_zero);
    cudaGetSymbolAddress((void**)&pHn,  g_hn);
    cudaGetSymbolAddress((void**)&pEmb, g_emb);
    cudaGetSymbolAddress((void**)&pSc,  g_scale);
    cudaGetSymbolAddress((void**)&pSh,  g_shift);
    cudaGetSymbolAddress((void**)&pSc4, g_scale4);
    cudaGetSymbolAddress((void**)&pSh4, g_shift4);
    cudaGetSymbolAddress((void**)&pSc5, g_scale5);
    cudaGetSymbolAddress((void**)&pSh5, g_shift5);

    transpose_kernel<<<(Bz * T0 * F0c + 255) / 256, 256>>>(input_x, pX0);

    // conv1: raw input, stats fused.  C=40,KW=5,dil=1, T 400->396, CK=200, N=6336
    conv_gemm_f16k16<5,1,0,true><<<dim3(99, 4, 1), 256>>>(
        conv1_w, conv1_b, pX0, pA, nullptr, nullptr, nullptr, nullptr,
        40, 400, 396, 200, 6336, 0, 0, 0);
    bn_finalize<<<1, 512>>>(bn1_g, bn1_b, pSc, pSh, 1.f / 6336.f);

    // conv2: BN1 applied on load.  C=512,KW=3,dil=2, T 396->392, CK=1536, N=6272
    conv_gemm_f16k16<3,2,1,true><<<dim3(98, 4, 1), 256>>>(
        conv2_w, conv2_b, pA, pB, nullptr, nullptr, pSc, pSh,
        512, 396, 392, 1536, 6272, 0, 0, 0);
    bn_finalize<<<1, 512>>>(bn2_g, bn2_b, pSc, pSh, 1.f / 6272.f);

    // conv3: BN2 applied on load.  C=512,KW=3,dil=4, T 392->384, CK=1536, N=6144
    conv_gemm_f16k16<3,4,1,true><<<dim3(96, 4, 1), 256>>>(
        conv3_w, conv3_b, pB, pA, nullptr, nullptr, pSc, pSh,
        512, 392, 384, 1536, 6144, 0, 0, 0);
    bn_finalize<<<1, 512>>>(bn3_g, bn3_b, pSc, pSh, 1.f / 6144.f);

    // lin4: BN3 applied on load. pointwise 512->512, T=384, CK=512, N=6144
    conv_gemm_f16k16<1,1,1,true><<<dim3(96, 4, 1), 256>>>(
        lin4_w, lin4_b, pA, pB, nullptr, nullptr, pSc, pSh,
        512, 384, 384, 512, 6144, 0, 0, 0);
    bn_finalize<<<1, 512>>>(bn4_g, bn4_b, pSc4, pSh4, 1.f / 6144.f);

    // lin5: BN4 applied on load (x4 raw in pB) -> x5 raw
    conv_gemm_f16k16<1,1,1,true><<<dim3(96, 4, 1), 256>>>(
        lin5_w, lin5_b, pB, pX5, nullptr, nullptr, pSc4, pSh4,
        512, 384, 384, 512, 6144, 0, 0, 0);
    bn_finalize<<<1, 512>>>(bn5_g, bn5_b, pSc5, pSh5, 1.f / 6144.f);

    // pooling: M[b,i,j] = sum_t bn4(x4)[b,i,t]*bn5(x5)[b,j,t]
    // A = x5 raw (BN5 by row), X = x4 raw (BN4 by n). No stats.
    conv_gemm_f16k16<1,1,2,false><<<dim3(8, 4, 16), 256>>>(
        pX5, pZero, pB, pM, pSc5, pSh5, pSc4, pSh4,
        384, 1, 1, 384, 512, Hc * T3c, Hc * T3c, Kbot);

    // bottleneck: stream 512MB of bot_w once, M-tiles staged in smem
    zero_h<<<16, 512>>>();
    bottleneck<<<dim3(16, 32), 512>>>(bot_w);

    bn2d_relu<<<1, 512>>>(bot_b, bnb_g, bnb_b);
    emb_kernel<<<16, 512>>>(pHn, emb_w, emb_b, pEmb);
    norm_kernel<<<16, 512>>>(pEmb, out);
}

// round 8
// speedup vs baseline: 1.7565x; 1.0575x over previous
#include <cuda_runtime.h>
#include <cuda_fp16.h>
#include <math.h>
#include <stdint.h>

// ---------------- problem constants ----------------
#define Bz   16
#define T0   400
#define F0c  40
#define Hc   512
#define T1c  396
#define T3c  384
#define Kbot (Hc*Hc)   // 262144

// ---------------- scratch (device globals; no allocs allowed) ----------------
__device__ float g_x0[Bz*F0c*T0];
__device__ float g_bufA[Bz*Hc*T1c];
__device__ float g_bufB[Bz*Hc*T1c];
__device__ float g_x5[Bz*Hc*T3c];
__device__ float g_M[Bz*Kbot];
__device__ float g_sum[Hc];
__device__ float g_sumsq[Hc];
__device__ float g_scale[Hc];
__device__ float g_shift[Hc];
__device__ float g_scale4[Hc];
__device__ float g_shift4[Hc];
__device__ float g_scale5[Hc];
__device__ float g_shift5[Hc];
__device__ float g_h[Bz*Hc];
__device__ float g_hn[Bz*Hc];
__device__ float g_emb[Bz*Hc];
__device__ float g_zero[Hc];

// ---------------- helpers ----------------
__device__ __forceinline__ void f16_split2(float x0, float x1, uint32_t& hw, uint32_t& lw)
{
    __half2 h = __floats2half2_rn(x0, x1);
    float2 hf = __half22float2(h);
    __half2 l = __floats2half2_rn(x0 - hf.x, x1 - hf.y);
    hw = *(uint32_t*)&h;
    lw = *(uint32_t*)&l;
}

__device__ __forceinline__ void mma_f16_k16(float* d, const uint32_t* a, const uint32_t* b)
{
    asm volatile(
        "mma.sync.aligned.m16n8k16.row.col.f32.f16.f16.f32 "
        "{%0,%1,%2,%3}, {%4,%5,%6,%7}, {%8,%9}, {%0,%1,%2,%3};"
        : "+f"(d[0]), "+f"(d[1]), "+f"(d[2]), "+f"(d[3])
        : "r"(a[0]), "r"(a[1]), "r"(a[2]), "r"(a[3]), "r"(b[0]), "r"(b[1]));
}

__device__ __forceinline__ void ldsm_x4(uint32_t* r, uint32_t saddr)
{
    asm volatile("ldmatrix.sync.aligned.m8n8.x4.shared.b16 {%0,%1,%2,%3}, [%4];"
        : "=r"(r[0]), "=r"(r[1]), "=r"(r[2]), "=r"(r[3]) : "r"(saddr));
}

__device__ __forceinline__ void sts_v2(uint32_t saddr, uint32_t v0, uint32_t v1)
{
    asm volatile("st.shared.v2.u32 [%0], {%1,%2};" :: "r"(saddr), "r"(v0), "r"(v1));
}

__device__ __forceinline__ float relu20(float v)
{
    return fminf(fmaxf(v, 0.f), 20.f);
}

// ---------------- transpose [B,1,T,F] -> [B,F,T] ----------------
__global__ void transpose_kernel(const float* __restrict__ in, float* __restrict__ out)
{
    int idx = blockIdx.x * blockDim.x + threadIdx.x;
    if (idx >= Bz * T0 * F0c) return;
    int c = idx % F0c;
    int t = (idx / F0c) % T0;
    int b = idx / (F0c * T0);
    out[(b * F0c + c) * T0 + t] = in[idx];
}

// ---------------- FP16x3 tensor-core conv-as-GEMM (k16 + ldmatrix) ----------------
// Smem tiles row-major: [row][16 fp16] = [row][8 words], row stride 12 words
// (12r mod 32 gives disjoint 4-bank windows across any 8 rows -> LDSM conflict-free).
// BM=128 BN=64 BK=16, 256 thr, 8 warps 2x4, warp tile 64x16, double-buffered.
#define RSTR 12
template<int KW, int DIL, int MODE, bool STATS>
__global__ __launch_bounds__(256, 3)
void conv_gemm_f16k16(const float* __restrict__ A, const float* __restrict__ bias,
                      const float* __restrict__ X, float* __restrict__ Y,
                      const float* __restrict__ scA, const float* __restrict__ shA,
                      const float* __restrict__ scB, const float* __restrict__ shB,
                      int C, int Tin, int Tout, int CK, int Ntot,
                      int strideA, int strideX, int strideY)
{
    A += (size_t)blockIdx.z * strideA;
    X += (size_t)blockIdx.z * strideX;
    Y += (size_t)blockIdx.z * strideY;

    __shared__ uint32_t AsH[2][128][RSTR];
    __shared__ uint32_t AsL[2][128][RSTR];
    __shared__ uint32_t BsH[2][64][RSTR];
    __shared__ uint32_t BsL[2][64][RSTR];
    __shared__ float sScB[Hc];
    __shared__ float sShB[Hc];

    const int tid  = threadIdx.x;
    const int lane = tid & 31;
    const int warp = tid >> 5;
    const int wm = warp >> 2;      // 0..1 (64 rows each)
    const int wn = warp & 3;       // 0..3 (16 cols each)
    const int oBase = blockIdx.y * 128;
    const int nBase = blockIdx.x * 64;

    float acc[4][2][4];
    #pragma unroll
    for (int i = 0; i < 4; i++)
        #pragma unroll
        for (int j = 0; j < 2; j++)
            #pragma unroll
            for (int r = 0; r < 4; r++) acc[i][j][r] = 0.f;

    // A loader: row = tid>>1; even thr floats {0-3,8-11} -> words {0,1,4,5};
    // odd thr floats {4-7,12-15} -> words {2,3,6,7}
    const int aRow = tid >> 1;
    const int aC0  = (tid & 1) * 4;
    const int aW   = (tid & 1) * 2;
    // B loader: n = tid&63, floats bG*4..+3 -> words bG*2, bG*2+1
    const int bN  = tid & 63;
    const int bG  = tid >> 6;

    const int nIdx = nBase + bN;
    const bool nValid = (nIdx < Ntot);
    int nb = 0, nt0 = 0;
    if (nValid) { nb = nIdx / Tout; nt0 = nIdx - nb * Tout; }
    const float* Xbase = X + ((size_t)nb * C) * Tin + nt0;
    const float* Arow = A + (size_t)(oBase + aRow) * CK;

    // smem base addresses (shared address space)
    const uint32_t baseAH = (uint32_t)__cvta_generic_to_shared(&AsH[0][0][0]);
    const uint32_t baseAL = (uint32_t)__cvta_generic_to_shared(&AsL[0][0][0]);
    const uint32_t baseBH = (uint32_t)__cvta_generic_to_shared(&BsH[0][0][0]);
    const uint32_t baseBL = (uint32_t)__cvta_generic_to_shared(&BsL[0][0][0]);
    const uint32_t bufA = 128 * RSTR * 4;   // bytes per A buffer
    const uint32_t bufB = 64 * RSTR * 4;

    // store addresses for this thread
    const uint32_t stA = (aRow * RSTR + aW) * 4;
    const uint32_t stB = (bN * RSTR + bG * 2) * 4;

    // LDSM source offsets:
    // A (x4): lanes 0-7 rows r0-7 kLow | 8-15 rows r8-15 kLow | 16-23 r0-7 kHi | 24-31 r8-15 kHi
    const int aFragRow = (lane & 7) + ((lane >> 3) & 1) * 8;
    const int aFragWord = (lane >> 4) * 4;
    const uint32_t ldA0 = ((wm * 64 + aFragRow) * RSTR + aFragWord) * 4;  // + mt*16*RSTR*4
    // B (x4): m0 (n0-7,kL)=b0/nt0, m1 (n0-7,kH)=b1/nt0, m2 (n8-15,kL)=b0/nt1, m3=b1/nt1
    const int bFragRow = (lane & 7) + ((lane >> 4) << 3);
    const int bFragWord = ((lane >> 3) & 1) * 4;
    const uint32_t ldB = ((wn * 16 + bFragRow) * RSTR + bFragWord) * 4;

    // per-thread BN constants for MODE 2
    float aS = 1.f, aSh = 0.f, bS = 1.f, bSh = 0.f;
    if (MODE == 2) {
        aS  = scA[oBase + aRow];
        aSh = shA[oBase + aRow];
        bS  = scB[nIdx & (Hc - 1)];
        bSh = shB[nIdx & (Hc - 1)];
    }
    if (MODE == 1) {
        for (int i = tid; i < C; i += 256) {
            sScB[i] = scB[i];
            sShB[i] = shB[i];
        }
        __syncthreads();
    }

    float pa[8], pb[4];

    // ---- prefetch k0 = 0 ----
    {
        const float4 av = *(const float4*)(Arow + aC0);
        pa[0] = av.x; pa[1] = av.y; pa[2] = av.z; pa[3] = av.w;
        if (aC0 + 11 < CK) {
            const float4 av2 = *(const float4*)(Arow + aC0 + 8);
            pa[4] = av2.x; pa[5] = av2.y; pa[6] = av2.z; pa[7] = av2.w;
        } else {
            pa[4] = pa[5] = pa[6] = pa[7] = 0.f;
        }
        if (MODE == 2) {
            #pragma unroll
            for (int j = 0; j < 8; j++) pa[j] = relu20(aS * pa[j] + aSh);
        }
        #pragma unroll
        for (int p = 0; p < 4; p++) {
            int kkg = bG * 4 + p;
            float v = 0.f;
            if (nValid && kkg < CK) {
                int c = kkg / KW;
                int kw = kkg - c * KW;
                v = Xbase[c * Tin + kw * DIL];
                if (MODE == 1) v = relu20(sScB[c] * v + sShB[c]);
                if (MODE == 2) v = relu20(bS * v + bSh);
            }
            pb[p] = v;
        }
    }

    const int nSteps = (CK + 15) >> 4;
    int pbuf = 0;
    for (int s = 0; s < nSteps; s++) {
        // stage current k16 tile (fp16 hi/lo split), vectorized stores
        {
            const uint32_t offA = pbuf * bufA;
            const uint32_t offB = pbuf * bufB;
            uint32_t h0, l0, h1, l1;
            f16_split2(pa[0], pa[1], h0, l0);
            f16_split2(pa[2], pa[3], h1, l1);
            sts_v2(baseAH + offA + stA, h0, h1);
            sts_v2(baseAL + offA + stA, l0, l1);
            f16_split2(pa[4], pa[5], h0, l0);
            f16_split2(pa[6], pa[7], h1, l1);
            sts_v2(baseAH + offA + stA + 16, h0, h1);
            sts_v2(baseAL + offA + stA + 16, l0, l1);
            f16_split2(pb[0], pb[1], h0, l0);
            f16_split2(pb[2], pb[3], h1, l1);
            sts_v2(baseBH + offB + stB, h0, h1);
            sts_v2(baseBL + offB + stB, l0, l1);
        }
        __syncthreads();

        // prefetch next k16 tile
        if (s + 1 < nSteps) {
            int k0 = (s + 1) * 16;
            const float4 av = *(const float4*)(Arow + k0 + aC0);
            pa[0] = av.x; pa[1] = av.y; pa[2] = av.z; pa[3] = av.w;
            if (k0 + aC0 + 11 < CK) {
                const float4 av2 = *(const float4*)(Arow + k0 + aC0 + 8);
                pa[4] = av2.x; pa[5] = av2.y; pa[6] = av2.z; pa[7] = av2.w;
            } else {
                pa[4] = pa[5] = pa[6] = pa[7] = 0.f;
            }
            if (MODE == 2) {
                #pragma unroll
                for (int j = 0; j < 8; j++) pa[j] = relu20(aS * pa[j] + aSh);
            }
            #pragma unroll
            for (int p = 0; p < 4; p++) {
                int kkg = k0 + bG * 4 + p;
                float v = 0.f;
                if (nValid && kkg < CK) {
                    int c = kkg / KW;
                    int kw = kkg - c * KW;
                    v = Xbase[c * Tin + kw * DIL];
                    if (MODE == 1) v = relu20(sScB[c] * v + sShB[c]);
                    if (MODE == 2) v = relu20(bS * v + bSh);
                }
                pb[p] = v;
            }
        }

        // fragment loads via ldmatrix
        {
            const uint32_t offA = pbuf * bufA;
            const uint32_t offB = pbuf * bufB;
            uint32_t bHf[4], bLf[4];
            ldsm_x4(bHf, baseBH + offB + ldB);
            ldsm_x4(bLf, baseBL + offB + ldB);
            #pragma unroll
            for (int mt = 0; mt < 4; mt++) {
                const uint32_t mtOff = mt * 16 * RSTR * 4;
                uint32_t aHf[4], aLf[4];
                ldsm_x4(aHf, baseAH + offA + ldA0 + mtOff);
                ldsm_x4(aLf, baseAL + offA + ldA0 + mtOff);
                #pragma unroll
                for (int nt = 0; nt < 2; nt++) {
                    mma_f16_k16(acc[mt][nt], aHf, bLf + nt * 2);
                    mma_f16_k16(acc[mt][nt], aLf, bHf + nt * 2);
                    mma_f16_k16(acc[mt][nt], aHf, bHf + nt * 2);
                }
            }
        }

        pbuf ^= 1;
    }

    // epilogue
    #pragma unroll
    for (int mt = 0; mt < 4; mt++) {
        int row0 = oBase + wm * 64 + mt * 16 + (lane >> 2);
        float b0 = bias[row0];
        float b1 = bias[row0 + 8];
        float s0 = 0.f, q0 = 0.f, s1 = 0.f, q1 = 0.f;
        #pragma unroll
        for (int nt = 0; nt < 2; nt++) {
            int col0 = nBase + wn * 16 + nt * 8 + (lane & 3) * 2;
            #pragma unroll
            for (int cc = 0; cc < 2; cc++) {
                int col = col0 + cc;
                if (col < Ntot) {
                    float v0 = acc[mt][nt][cc]     + b0;
                    float v1 = acc[mt][nt][2 + cc] + b1;
                    int b = col / Tout;
                    int t = col - b * Tout;
                    size_t base = ((size_t)b * Hc) * Tout + t;
                    Y[base + (size_t)row0 * Tout]       = v0;
                    Y[base + (size_t)(row0 + 8) * Tout] = v1;
                    if (STATS) {
                        s0 += v0; q0 += v0 * v0;
                        s1 += v1; q1 += v1 * v1;
                    }
                }
            }
        }
        if (STATS) {
            #pragma unroll
            for (int off = 2; off >= 1; off >>= 1) {
                s0 += __shfl_down_sync(0xffffffffu, s0, off);
                q0 += __shfl_down_sync(0xffffffffu, q0, off);
                s1 += __shfl_down_sync(0xffffffffu, s1, off);
                q1 += __shfl_down_sync(0xffffffffu, q1, off);
            }
            if ((lane & 3) == 0) {
                atomicAdd(&g_sum[row0], s0);
                atomicAdd(&g_sumsq[row0], q0);
                atomicAdd(&g_sum[row0 + 8], s1);
                atomicAdd(&g_sumsq[row0 + 8], q1);
            }
        }
    }
}

// ---------------- BN finalize ----------------
__global__ void bn_finalize(const float* __restrict__ g, const float* __restrict__ be,
                            float* __restrict__ sc, float* __restrict__ sh, float invN)
{
    int c = threadIdx.x;   // 512
    float s = g_sum[c], q = g_sumsq[c];
    float m = s * invN;
    float var = q * invN - m * m;
    float a = g[c] * rsqrtf(var + 1e-5f);
    sc[c] = a;
    sh[c] = be[c] - a * m;
    g_sum[c] = 0.f;
    g_sumsq[c] = 0.f;
}

// ---------------- bottleneck ----------------
__global__ void zero_h()
{
    g_h[blockIdx.x * blockDim.x + threadIdx.x] = 0.f;
}

__global__ __launch_bounds__(512)
void bottleneck(const float* __restrict__ W)
{
    __shared__ float Ms[Bz][512];
    int warp = threadIdx.x >> 5, lane = threadIdx.x & 31;
    int o0 = blockIdx.x * 32 + warp * 2;
    int k0 = blockIdx.y * (Kbot / 32);

    float acc0[16], acc1[16];
    #pragma unroll
    for (int b = 0; b < 16; b++) { acc0[b] = 0.f; acc1[b] = 0.f; }

    for (int kt = 0; kt < Kbot / 32; kt += 512) {
        __syncthreads();
        #pragma unroll
        for (int i = 0; i < 16; i++) {
            int idx = threadIdx.x + i * 512;
            int b = idx >> 9, kk = idx & 511;
            Ms[b][kk] = g_M[b * Kbot + k0 + kt + kk];
        }
        __syncthreads();
        const float* w0p = W + (size_t)o0 * Kbot + k0 + kt;
        const float* w1p = w0p + Kbot;
        #pragma unroll
        for (int kk = lane * 4; kk < 512; kk += 128) {
            float4 w0 = *(const float4*)(w0p + kk);
            float4 w1 = *(const float4*)(w1p + kk);
            #pragma unroll
            for (int b = 0; b < 16; b++) {
                float4 m = *(const float4*)&Ms[b][kk];
                acc0[b] += w0.x * m.x + w0.y * m.y + w0.z * m.z + w0.w * m.w;
                acc1[b] += w1.x * m.x + w1.y * m.y + w1.z * m.z + w1.w * m.w;
            }
        }
    }
    #pragma unroll
    for (int b = 0; b < 16; b++) {
        float v0 = acc0[b], v1 = acc1[b];
        #pragma unroll
        for (int off = 16; off; off >>= 1) {
            v0 += __shfl_down_sync(0xffffffffu, v0, off);
            v1 += __shfl_down_sync(0xffffffffu, v1, off);
        }
        if (lane == 0) {
            atomicAdd(&g_h[b * Hc + o0], v0);
            atomicAdd(&g_h[b * Hc + o0 + 1], v1);
        }
    }
}

// ---------------- BN over batch + relu20 ----------------
__global__ void bn2d_relu(const float* __restrict__ bot_b, const float* __restrict__ gg,
                          const float* __restrict__ gb)
{
    int o = threadIdx.x;
    float v[16];
    float s = 0.f, sq = 0.f;
    #pragma unroll
    for (int b = 0; b < 16; b++) {
        float x = g_h[b * Hc + o] + bot_b[o];
        v[b] = x; s += x; sq += x * x;
    }
    float m = s * (1.f / 16.f);
    float var = sq * (1.f / 16.f) - m * m;
    float a = gg[o] * rsqrtf(var + 1e-5f);
    float d = gb[o] - a * m;
    #pragma unroll
    for (int b = 0; b < 16; b++) {
        float z = a * v[b] + d;
        g_hn[b * Hc + o] = fminf(fmaxf(z, 0.f), 20.f);
    }
}

// ---------------- embedding GEMV + bias ----------------
__global__ void emb_kernel(const float* __restrict__ h, const float* __restrict__ W,
                           const float* __restrict__ bias, float* __restrict__ emb)
{
    int b = blockIdx.x;
    int warp = threadIdx.x >> 5, lane = threadIdx.x & 31;
    __shared__ float hs[512];
    hs[threadIdx.x] = h[b * Hc + threadIdx.x];
    __syncthreads();
    for (int e = warp; e < 512; e += 16) {
        float s = 0.f;
        for (int c = lane; c < 512; c += 32)
            s += hs[c] * W[e * 512 + c];
        #pragma unroll
        for (int off = 16; off; off >>= 1)
            s += __shfl_down_sync(0xffffffffu, s, off);
        if (lane == 0) emb[b * Hc + e] = s + bias[e];
    }
}

// ---------------- L2 normalize * 10 ----------------
__global__ void norm_kernel(const float* __restrict__ emb, float* __restrict__ out)
{
    int b = blockIdx.x;
    int t = threadIdx.x;
    __shared__ float red[512];
    float v = emb[b * 512 + t];
    red[t] = v * v;
    __syncthreads();
    for (int s = 256; s > 0; s >>= 1) {
        if (t < s) red[t] += red[t + s];
        __syncthreads();
    }
    float scale = 10.f / sqrtf(red[0] + 1e-10f);
    out[b * 512 + t] = v * scale;
}

// ---------------- launcher ----------------
extern "C" void kernel_launch(void* const* d_in, const int* in_sizes, int n_in,
                              void* d_out, int out_size)
{
    const float* input_x = (const float*)d_in[0];
    const float* conv1_w = (const float*)d_in[1];
    const float* conv1_b = (const float*)d_in[2];
    const float* bn1_g   = (const float*)d_in[3];
    const float* bn1_b   = (const float*)d_in[4];
    const float* conv2_w = (const float*)d_in[5];
    const float* conv2_b = (const float*)d_in[6];
    const float* bn2_g   = (const float*)d_in[7];
    const float* bn2_b   = (const float*)d_in[8];
    const float* conv3_w = (const float*)d_in[9];
    const float* conv3_b = (const float*)d_in[10];
    const float* bn3_g   = (const float*)d_in[11];
    const float* bn3_b   = (const float*)d_in[12];
    const float* lin4_w  = (const float*)d_in[13];
    const float* lin4_b  = (const float*)d_in[14];
    const float* bn4_g   = (const float*)d_in[15];
    const float* bn4_b   = (const float*)d_in[16];
    const float* lin5_w  = (const float*)d_in[17];
    const float* lin5_b  = (const float*)d_in[18];
    const float* bn5_g   = (const float*)d_in[19];
    const float* bn5_b   = (const float*)d_in[20];
    const float* bot_w   = (const float*)d_in[21];
    const float* bot_b   = (const float*)d_in[22];
    const float* bnb_g   = (const float*)d_in[23];
    const float* bnb_b   = (const float*)d_in[24];
    const float* emb_w   = (const float*)d_in[25];
    const float* emb_b   = (const float*)d_in[26];
    float* out = (float*)d_out;

    float *pX0, *pA, *pB, *pX5, *pM, *pZero, *pHn, *pEmb;
    float *pSc, *pSh, *pSc4, *pSh4, *pSc5, *pSh5;
    cudaGetSymbolAddress((void**)&pX0,  g_x0);
    cudaGetSymbolAddress((void**)&pA,   g_bufA);
    cudaGetSymbolAddress((void**)&pB,   g_bufB);
    cudaGetSymbolAddress((void**)&pX5,  g_x5);
    cudaGetSymbolAddress((void**)&pM,   g_M);
    cudaGetSymbolAddress((void**)&pZero,g_zero);
    cudaGetSymbolAddress((void**)&pHn,  g_hn);
    cudaGetSymbolAddress((void**)&pEmb, g_emb);
    cudaGetSymbolAddress((void**)&pSc,  g_scale);
    cudaGetSymbolAddress((void**)&pSh,  g_shift);
    cudaGetSymbolAddress((void**)&pSc4, g_scale4);
    cudaGetSymbolAddress((void**)&pSh4, g_shift4);
    cudaGetSymbolAddress((void**)&pSc5, g_scale5);
    cudaGetSymbolAddress((void**)&pSh5, g_shift5);

    transpose_kernel<<<(Bz * T0 * F0c + 255) / 256, 256>>>(input_x, pX0);

    // conv1: C=40,KW=5,dil=1, T 400->396, CK=200, N=6336
    conv_gemm_f16k16<5,1,0,true><<<dim3(99, 4, 1), 256>>>(
        conv1_w, conv1_b, pX0, pA, nullptr, nullptr, nullptr, nullptr,
        40, 400, 396, 200, 6336, 0, 0, 0);
    bn_finalize<<<1, 512>>>(bn1_g, bn1_b, pSc, pSh, 1.f / 6336.f);

    // conv2: C=512,KW=3,dil=2, T 396->392, CK=1536, N=6272
    conv_gemm_f16k16<3,2,1,true><<<dim3(98, 4, 1), 256>>>(
        conv2_w, conv2_b, pA, pB, nullptr, nullptr, pSc, pSh,
        512, 396, 392, 1536, 6272, 0, 0, 0);
    bn_finalize<<<1, 512>>>(bn2_g, bn2_b, pSc, pSh, 1.f / 6272.f);

    // conv3: C=512,KW=3,dil=4, T 392->384, CK=1536, N=6144
    conv_gemm_f16k16<3,4,1,true><<<dim3(96, 4, 1), 256>>>(
        conv3_w, conv3_b, pB, pA, nullptr, nullptr, pSc, pSh,
        512, 392, 384, 1536, 6144, 0, 0, 0);
    bn_finalize<<<1, 512>>>(bn3_g, bn3_b, pSc, pSh, 1.f / 6144.f);

    // lin4: pointwise 512->512, T=384, CK=512, N=6144
    conv_gemm_f16k16<1,1,1,true><<<dim3(96, 4, 1), 256>>>(
        lin4_w, lin4_b, pA, pB, nullptr, nullptr, pSc, pSh,
        512, 384, 384, 512, 6144, 0, 0, 0);
    bn_finalize<<<1, 512>>>(bn4_g, bn4_b, pSc4, pSh4, 1.f / 6144.f);

    // lin5: BN4 applied on load (x4 raw in pB) -> x5 raw
    conv_gemm_f16k16<1,1,1,true><<<dim3(96, 4, 1), 256>>>(
        lin5_w, lin5_b, pB, pX5, nullptr, nullptr, pSc4, pSh4,
        512, 384, 384, 512, 6144, 0, 0, 0);
    bn_finalize<<<1, 512>>>(bn5_g, bn5_b, pSc5, pSh5, 1.f / 6144.f);

    // pooling: M[b,i,j] = sum_t bn4(x4)[b,i,t]*bn5(x5)[b,j,t]
    conv_gemm_f16k16<1,1,2,false><<<dim3(8, 4, 16), 256>>>(
        pX5, pZero, pB, pM, pSc5, pSh5, pSc4, pSh4,
        384, 1, 1, 384, 512, Hc * T3c, Hc * T3c, Kbot);

    // bottleneck: stream 512MB of bot_w once
    zero_h<<<16, 512>>>();
    bottleneck<<<dim3(16, 32), 512>>>(bot_w);

    bn2d_relu<<<1, 512>>>(bot_b, bnb_g, bnb_b);
    emb_kernel<<<16, 512>>>(pHn, emb_w, emb_b, pEmb);
    norm_kernel<<<16, 512>>>(pEmb, out);
}